// round 4
// baseline (speedup 1.0000x reference)
#include <cuda_runtime.h>

#define N_MAX 131072
#define E_MAX 2100000

// scratch (static __device__ arrays; no allocation)
__device__ float g_h [N_MAX * 64];   // projected features
__device__ float g_as[N_MAX * 8];    // a_src per node/head
__device__ float g_ad[N_MAX * 8];    // a_dst per node/head
__device__ int   g_deg[N_MAX + 1];
__device__ int   g_row[N_MAX + 1];   // CSR row starts (by dst)
__device__ int   g_cur[N_MAX];
__device__ int   g_csr[E_MAX];       // src node per CSR slot

// ---------------------------------------------------------------------------
// 0) zero degree + cursor
__global__ void zero_kernel(int N) {
    int i = blockIdx.x * blockDim.x + threadIdx.x;
    if (i < N) { g_deg[i] = 0; g_cur[i] = 0; }
}

// 1) in-degree histogram over dst (edge_index is int32: JAX x64 disabled)
__global__ void degree_kernel(const int* __restrict__ ei, int E, int N) {
    int e = blockIdx.x * blockDim.x + threadIdx.x;
    if (e < E) {
        int d = ei[E + e];
        if ((unsigned)d < (unsigned)N) atomicAdd(&g_deg[d], 1);
    }
}

// 2) exclusive scan (single block, chunked with carry)
__global__ void scan_kernel(int N) {
    __shared__ int wsum[32];
    __shared__ int s_carry;
    int tid = threadIdx.x, lane = tid & 31, wid = tid >> 5;
    if (tid == 0) s_carry = 0;
    __syncthreads();
    for (int base = 0; base < N; base += 1024) {
        int i = base + tid;
        int v = (i < N) ? g_deg[i] : 0;
        int x = v;
        #pragma unroll
        for (int o = 1; o < 32; o <<= 1) {
            int y = __shfl_up_sync(0xffffffffu, x, o);
            if (lane >= o) x += y;
        }
        if (lane == 31) wsum[wid] = x;
        __syncthreads();
        if (wid == 0) {
            int s = wsum[lane];
            #pragma unroll
            for (int o = 1; o < 32; o <<= 1) {
                int y = __shfl_up_sync(0xffffffffu, s, o);
                if (lane >= o) s += y;
            }
            wsum[lane] = s;
        }
        __syncthreads();
        int prefix = s_carry + ((wid > 0) ? wsum[wid - 1] : 0);
        if (i < N) g_row[i] = prefix + x - v;   // exclusive
        __syncthreads();
        if (tid == 0) s_carry += wsum[31];
        __syncthreads();
    }
    if (threadIdx.x == 0) g_row[N] = s_carry;
}

// 3) scatter edges into CSR slots
__global__ void scatter_kernel(const int* __restrict__ ei, int E, int N) {
    int e = blockIdx.x * blockDim.x + threadIdx.x;
    if (e < E) {
        int s = ei[e];
        int d = ei[E + e];
        if ((unsigned)d < (unsigned)N && (unsigned)s < (unsigned)N) {
            int pos = atomicAdd(&g_cur[d], 1);
            g_csr[g_row[d] + pos] = s;
        }
    }
}

// ---------------------------------------------------------------------------
// 4) fused GEMM h = x@W  +  a_src/a_dst reductions
//    block: 256 threads, 16 nodes, W (128x64) + 16 x-rows staged in smem
__global__ void gemm_att_kernel(const float* __restrict__ x,
                                const float* __restrict__ W,
                                const float* __restrict__ attS,
                                const float* __restrict__ attD, int N) {
    __shared__ float ws[128 * 64];   // 32 KB
    __shared__ float xs[16 * 128];   //  8 KB
    int t = threadIdx.x;
    int node0 = blockIdx.x * 16;

    #pragma unroll
    for (int i = 0; i < 8; i++)
        ((float4*)ws)[t + 256 * i] = ((const float4*)W)[t + 256 * i];

    #pragma unroll
    for (int i = 0; i < 2; i++) {
        int idx = t + 256 * i;          // float4 index in [0,512)
        int n = node0 + (idx >> 5);     // 32 float4 per row
        float4 v = make_float4(0.f, 0.f, 0.f, 0.f);
        if (n < N) v = ((const float4*)x)[(long)n * 32 + (idx & 31)];
        ((float4*)xs)[idx] = v;
    }
    __syncthreads();

    int c = t & 63;          // output channel
    int rgrp = t >> 6;       // 0..3
    float acc[4] = {0.f, 0.f, 0.f, 0.f};
    #pragma unroll
    for (int k = 0; k < 128; k += 4) {
        float w0 = ws[(k    ) * 64 + c];
        float w1 = ws[(k + 1) * 64 + c];
        float w2 = ws[(k + 2) * 64 + c];
        float w3 = ws[(k + 3) * 64 + c];
        #pragma unroll
        for (int j = 0; j < 4; j++) {
            const float4 xv = *(const float4*)&xs[(rgrp + 4 * j) * 128 + k];
            acc[j] += xv.x * w0 + xv.y * w1 + xv.z * w2 + xv.w * w3;
        }
    }

    float aS = attS[c], aD = attD[c];
    #pragma unroll
    for (int j = 0; j < 4; j++) {
        int n = node0 + rgrp + 4 * j;
        if (n < N) {
            g_h[(long)n * 64 + c] = acc[j];
            float vs = acc[j] * aS;
            float vd = acc[j] * aD;
            vs += __shfl_down_sync(0xffffffffu, vs, 4);
            vs += __shfl_down_sync(0xffffffffu, vs, 2);
            vs += __shfl_down_sync(0xffffffffu, vs, 1);
            vd += __shfl_down_sync(0xffffffffu, vd, 4);
            vd += __shfl_down_sync(0xffffffffu, vd, 2);
            vd += __shfl_down_sync(0xffffffffu, vd, 1);
            if ((c & 7) == 0) {
                g_as[n * 8 + (c >> 3)] = vs;
                g_ad[n * 8 + (c >> 3)] = vd;
            }
        }
    }
}

// ---------------------------------------------------------------------------
// 5) warp-per-node softmax + gather aggregation (2-pass: max, then exp-sum+acc)
__global__ void aggregate_kernel(const float* __restrict__ bias,
                                 float* __restrict__ out, int N) {
    int warp = (blockIdx.x * blockDim.x + threadIdx.x) >> 5;
    int lane = threadIdx.x & 31;
    if (warp >= N) return;
    int n  = warp;
    int c0 = lane * 2;       // 2 channels per lane
    int hl = lane >> 2;      // head for this lane

    float adn = g_ad[n * 8 + hl];
    float asn = g_as[n * 8 + hl];
    int rs = g_row[n], re = g_row[n + 1];

    float e0 = asn + adn;
    float eself = fmaxf(e0, 0.2f * e0);
    float m = eself;
    for (int i = rs; i < re; i++) {
        int s = g_csr[i];
        float e = g_as[s * 8 + hl] + adn;
        m = fmaxf(m, fmaxf(e, 0.2f * e));
    }

    float ex   = __expf(eself - m);
    float ssum = ex;
    float2 hv  = *(const float2*)&g_h[(long)n * 64 + c0];
    float acc0 = ex * hv.x;
    float acc1 = ex * hv.y;
    for (int i = rs; i < re; i++) {
        int s = g_csr[i];
        float e  = g_as[s * 8 + hl] + adn;
        float el = fmaxf(e, 0.2f * e);
        float xv = __expf(el - m);
        ssum += xv;
        float2 hs = *(const float2*)&g_h[(long)s * 64 + c0];
        acc0 += xv * hs.x;
        acc1 += xv * hs.y;
    }
    float inv = 1.0f / ssum;
    out[(long)n * 64 + c0    ] = acc0 * inv + bias[c0];
    out[(long)n * 64 + c0 + 1] = acc1 * inv + bias[c0 + 1];
}

// ---------------------------------------------------------------------------
extern "C" void kernel_launch(void* const* d_in, const int* in_sizes, int n_in,
                              void* d_out, int out_size) {
    const float* x    = (const float*)d_in[0];
    const int*   ei   = (const int*)d_in[1];
    const float* W    = (const float*)d_in[2];
    const float* attS = (const float*)d_in[3];
    const float* attD = (const float*)d_in[4];
    const float* bias = (const float*)d_in[5];
    float*       out  = (float*)d_out;

    int N = in_sizes[0] / 128;
    int E = in_sizes[1] / 2;

    zero_kernel    <<<(N + 255) / 256, 256>>>(N);
    degree_kernel  <<<(E + 255) / 256, 256>>>(ei, E, N);
    scan_kernel    <<<1, 1024>>>(N);
    scatter_kernel <<<(E + 255) / 256, 256>>>(ei, E, N);
    gemm_att_kernel<<<(N + 15) / 16, 256>>>(x, W, attS, attD, N);
    aggregate_kernel<<<(N * 32 + 255) / 256, 256>>>(bias, out, N);
}

// round 6
// speedup vs baseline: 1.6033x; 1.6033x over previous
#include <cuda_runtime.h>

#define N_MAX 131072
#define E_MAX 2100000

// scratch (static __device__ arrays; no allocation)
__device__ float g_h [N_MAX * 64];   // projected features
__device__ float g_as[N_MAX * 8];    // a_src per node/head
__device__ float g_ad[N_MAX * 8];    // a_dst per node/head
__device__ float g_wt[64 * 128];     // W transposed: [c][k]
__device__ int   g_deg[N_MAX];
__device__ int   g_row[N_MAX];       // CSR row start (by dst, unordered bases)
__device__ int   g_cur[N_MAX];
__device__ int   g_csr[E_MAX];       // src node per CSR slot
__device__ int   g_total;

// ---------------------------------------------------------------------------
// 0) zero degree + global counter
__global__ void zero_kernel(int N) {
    int i = blockIdx.x * blockDim.x + threadIdx.x;
    if (i < N) g_deg[i] = 0;
    if (i == 0) g_total = 0;
}

// 1) in-degree histogram over dst (edge_index is int32)
__global__ void degree_kernel(const int* __restrict__ ei, int E, int N) {
    int e = blockIdx.x * blockDim.x + threadIdx.x;
    if (e < E) {
        int d = ei[E + e];
        if ((unsigned)d < (unsigned)N) atomicAdd(&g_deg[d], 1);
    }
}

// 2) row-base assignment: warp-aggregated atomic offsets (bases unordered = fine)
__global__ void offsets_kernel(int N) {
    int i = blockIdx.x * blockDim.x + threadIdx.x;
    int lane = threadIdx.x & 31;
    int v = (i < N) ? g_deg[i] : 0;
    int xsum = v;
    #pragma unroll
    for (int o = 1; o < 32; o <<= 1) {
        int y = __shfl_up_sync(0xffffffffu, xsum, o);
        if (lane >= o) xsum += y;
    }
    int tot = __shfl_sync(0xffffffffu, xsum, 31);
    int base = 0;
    if (lane == 31) base = atomicAdd(&g_total, tot);
    base = __shfl_sync(0xffffffffu, base, 31);
    if (i < N) {
        int st = base + xsum - v;
        g_row[i] = st;
        g_cur[i] = st;
    }
}

// 3) scatter edges into CSR slots
__global__ void scatter_kernel(const int* __restrict__ ei, int E, int N) {
    int e = blockIdx.x * blockDim.x + threadIdx.x;
    if (e < E) {
        int s = ei[e];
        int d = ei[E + e];
        if ((unsigned)d < (unsigned)N && (unsigned)s < (unsigned)N) {
            int pos = atomicAdd(&g_cur[d], 1);
            g_csr[pos] = s;
        }
    }
}

// ---------------------------------------------------------------------------
// 3b) transpose W once: g_wt[c*128 + k] = W[k*64 + c]
__global__ void wt_kernel(const float* __restrict__ W) {
    int idx = blockIdx.x * blockDim.x + threadIdx.x;
    if (idx < 64 * 128) {
        int c = idx & 63;
        int k = idx >> 6;
        g_wt[c * 128 + k] = W[idx];
    }
}

// ---------------------------------------------------------------------------
// 4) GEMM h = x@W via fma.rn.f32x2, 8 nodes x 8 channels per thread,
//    128 threads/block, 128 nodes/block; + fused a_src/a_dst reduction.
#define XS_STRIDE 36   // 32 k + pad4 (bank step 4 per node)
#define WS_STRIDE 36   // 32 k + pad4 (bank step 4 per channel)

#define FFMA2(d, a, b) asm("fma.rn.f32x2 %0, %1, %2, %0;" : "+l"(d) : "l"(a), "l"(b))

__global__ __launch_bounds__(128) void gemm_att_kernel(
        const float* __restrict__ x,
        const float* __restrict__ attS,
        const float* __restrict__ attD, int N) {
    __shared__ float ws[64 * WS_STRIDE];    //  9216 B (per-k-chunk W slice)
    __shared__ float xs[128 * XS_STRIDE];   // 18432 B
    int t = threadIdx.x;
    int cg = t & 7;        // channel group: c = cg + 8*i  (i == head!)
    int ng = t >> 3;       // node group:    n = node0 + ng + 16*j
    int node0 = blockIdx.x * 128;

    unsigned long long acc[8][8];
    #pragma unroll
    for (int j = 0; j < 8; j++)
        #pragma unroll
        for (int i = 0; i < 8; i++) acc[j][i] = 0ull;

    for (int kc = 0; kc < 4; kc++) {       // 4 chunks of 32 k
        __syncthreads();
        // stage W chunk: 64c x 32k = 512 float4, 4 per thread (coalesced from g_wt)
        #pragma unroll
        for (int p = 0; p < 4; p++) {
            int idx = t + 128 * p;          // 0..511
            int c  = idx >> 3;
            int k4 = idx & 7;
            float4 v = ((const float4*)g_wt)[c * 32 + kc * 8 + k4];
            *(float4*)&ws[c * WS_STRIDE + k4 * 4] = v;
        }
        // stage x chunk: 128n x 32k = 1024 float4, 8 per thread
        #pragma unroll
        for (int p = 0; p < 8; p++) {
            int idx = t + 128 * p;          // 0..1023
            int nn = idx >> 3;
            int k4 = idx & 7;
            int n = node0 + nn;
            float4 v = make_float4(0.f, 0.f, 0.f, 0.f);
            if (n < N) v = ((const float4*)x)[n * 32 + kc * 8 + k4];
            *(float4*)&xs[nn * XS_STRIDE + k4 * 4] = v;
        }
        __syncthreads();

        #pragma unroll
        for (int k4 = 0; k4 < 8; k4++) {
            ulonglong2 wv[8], xv[8];
            #pragma unroll
            for (int i = 0; i < 8; i++)
                wv[i] = *(const ulonglong2*)&ws[(cg + 8 * i) * WS_STRIDE + k4 * 4];
            #pragma unroll
            for (int j = 0; j < 8; j++)
                xv[j] = *(const ulonglong2*)&xs[(ng + 16 * j) * XS_STRIDE + k4 * 4];
            #pragma unroll
            for (int j = 0; j < 8; j++)
                #pragma unroll
                for (int i = 0; i < 8; i++) {
                    FFMA2(acc[j][i], xv[j].x, wv[i].x);
                    FFMA2(acc[j][i], xv[j].y, wv[i].y);
                }
        }
    }

    // epilogue: unpack, store h, reduce attention logits per head
    float aS[8], aD[8];
    #pragma unroll
    for (int i = 0; i < 8; i++) { aS[i] = attS[cg + 8 * i]; aD[i] = attD[cg + 8 * i]; }

    #pragma unroll
    for (int j = 0; j < 8; j++) {
        int n = node0 + ng + 16 * j;
        bool valid = (n < N);
        #pragma unroll
        for (int i = 0; i < 8; i++) {
            union { unsigned long long u; float2 f; } cv;
            cv.u = acc[j][i];
            float v = cv.f.x + cv.f.y;
            if (valid) g_h[(long)n * 64 + cg + 8 * i] = v;
            float ps = v * aS[i];
            float pd = v * aD[i];
            ps += __shfl_down_sync(0xffffffffu, ps, 4, 8);
            ps += __shfl_down_sync(0xffffffffu, ps, 2, 8);
            ps += __shfl_down_sync(0xffffffffu, ps, 1, 8);
            pd += __shfl_down_sync(0xffffffffu, pd, 4, 8);
            pd += __shfl_down_sync(0xffffffffu, pd, 2, 8);
            pd += __shfl_down_sync(0xffffffffu, pd, 1, 8);
            if (cg == 0 && valid) {
                g_as[n * 8 + i] = ps;
                g_ad[n * 8 + i] = pd;
            }
        }
    }
}

// ---------------------------------------------------------------------------
// 5) warp-per-node softmax + gather, SINGLE pass (no max subtraction:
//    logits are O(1), exp overflow impossible; softmax is shift-invariant)
__global__ void aggregate_kernel(const float* __restrict__ bias,
                                 float* __restrict__ out, int N) {
    int warp = (blockIdx.x * blockDim.x + threadIdx.x) >> 5;
    int lane = threadIdx.x & 31;
    if (warp >= N) return;
    int n  = warp;
    int c0 = lane * 2;       // 2 channels per lane
    int hl = lane >> 2;      // head for this lane

    float adn = g_ad[n * 8 + hl];
    float asn = g_as[n * 8 + hl];
    int rs = g_row[n];
    int re = rs + g_deg[n];

    // self loop
    float e0 = asn + adn;
    e0 = fmaxf(e0, 0.2f * e0);
    float ex = __expf(e0);
    float ssum = ex;
    float2 hv = *(const float2*)&g_h[(long)n * 64 + c0];
    float a0 = ex * hv.x;
    float a1 = ex * hv.y;

    int s = (rs < re) ? g_csr[rs] : 0;
    for (int i = rs; i < re; i++) {
        int sn = (i + 1 < re) ? g_csr[i + 1] : 0;   // prefetch next src
        float as = g_as[s * 8 + hl];
        float2 hs = *(const float2*)&g_h[(long)s * 64 + c0];
        float e = as + adn;
        e = fmaxf(e, 0.2f * e);
        float xv = __expf(e);
        ssum += xv;
        a0 += xv * hs.x;
        a1 += xv * hs.y;
        s = sn;
    }
    float inv = 1.0f / ssum;
    out[(long)n * 64 + c0    ] = a0 * inv + bias[c0];
    out[(long)n * 64 + c0 + 1] = a1 * inv + bias[c0 + 1];
}

// ---------------------------------------------------------------------------
extern "C" void kernel_launch(void* const* d_in, const int* in_sizes, int n_in,
                              void* d_out, int out_size) {
    const float* x    = (const float*)d_in[0];
    const int*   ei   = (const int*)d_in[1];
    const float* W    = (const float*)d_in[2];
    const float* attS = (const float*)d_in[3];
    const float* attD = (const float*)d_in[4];
    const float* bias = (const float*)d_in[5];
    float*       out  = (float*)d_out;

    int N = in_sizes[0] / 128;
    int E = in_sizes[1] / 2;

    zero_kernel     <<<(N + 255) / 256, 256>>>(N);
    degree_kernel   <<<(E + 255) / 256, 256>>>(ei, E, N);
    offsets_kernel  <<<(N + 255) / 256, 256>>>(N);
    scatter_kernel  <<<(E + 255) / 256, 256>>>(ei, E, N);
    wt_kernel       <<<(64 * 128 + 255) / 256, 256>>>(W);
    gemm_att_kernel <<<(N + 127) / 128, 128>>>(x, attS, attD, N);
    aggregate_kernel<<<((long)N * 32 + 255) / 256, 256>>>(bias, out, N);
}

// round 7
// speedup vs baseline: 1.7062x; 1.0642x over previous
#include <cuda_runtime.h>
#include <cuda_fp16.h>

#define N_MAX 131072
#define E_MAX 2100000

// scratch (static __device__ arrays; no allocation)
__device__ __half g_hh[N_MAX * 64]; // projected features (fp16 storage, fp32 math)
__device__ float g_as[N_MAX * 8];    // a_src per node/head
__device__ float g_ad[N_MAX * 8];    // a_dst per node/head
__device__ float g_wt[64 * 128];     // W transposed: [c][k]
__device__ int   g_deg[N_MAX];
__device__ int   g_row[N_MAX];       // CSR row start (by dst, unordered bases)
__device__ int   g_cur[N_MAX];
__device__ int   g_csr[E_MAX];       // src node per CSR slot
__device__ int   g_total;

// ---------------------------------------------------------------------------
// 0) zero degree + global counter
__global__ void zero_kernel(int N) {
    int i = blockIdx.x * blockDim.x + threadIdx.x;
    if (i < N) g_deg[i] = 0;
    if (i == 0) g_total = 0;
}

// 1) in-degree histogram over dst; 2 independent coalesced edges per thread
__global__ void degree_kernel(const int* __restrict__ ei, int E, int N) {
    int half = (E + 1) >> 1;
    int e = blockIdx.x * blockDim.x + threadIdx.x;
    if (e < half) {
        int d0 = ei[E + e];
        int e1 = e + half;
        if ((unsigned)d0 < (unsigned)N) atomicAdd(&g_deg[d0], 1);
        if (e1 < E) {
            int d1 = ei[E + e1];
            if ((unsigned)d1 < (unsigned)N) atomicAdd(&g_deg[d1], 1);
        }
    }
}

// 2) row-base assignment: warp-aggregated atomic offsets (bases unordered = fine)
__global__ void offsets_kernel(int N) {
    int i = blockIdx.x * blockDim.x + threadIdx.x;
    int lane = threadIdx.x & 31;
    int v = (i < N) ? g_deg[i] : 0;
    int xsum = v;
    #pragma unroll
    for (int o = 1; o < 32; o <<= 1) {
        int y = __shfl_up_sync(0xffffffffu, xsum, o);
        if (lane >= o) xsum += y;
    }
    int tot = __shfl_sync(0xffffffffu, xsum, 31);
    int base = 0;
    if (lane == 31) base = atomicAdd(&g_total, tot);
    base = __shfl_sync(0xffffffffu, base, 31);
    if (i < N) {
        int st = base + xsum - v;
        g_row[i] = st;
        g_cur[i] = st;
    }
}

// 3) scatter edges into CSR slots; 2 independent coalesced edges per thread
__global__ void scatter_kernel(const int* __restrict__ ei, int E, int N) {
    int half = (E + 1) >> 1;
    int e = blockIdx.x * blockDim.x + threadIdx.x;
    if (e >= half) return;
    int s0 = ei[e];
    int d0 = ei[E + e];
    int e1 = e + half;
    int s1 = 0, d1 = -1;
    if (e1 < E) { s1 = ei[e1]; d1 = ei[E + e1]; }
    if ((unsigned)d0 < (unsigned)N && (unsigned)s0 < (unsigned)N) {
        int pos = atomicAdd(&g_cur[d0], 1);
        g_csr[pos] = s0;
    }
    if ((unsigned)d1 < (unsigned)N && (unsigned)s1 < (unsigned)N) {
        int pos = atomicAdd(&g_cur[d1], 1);
        g_csr[pos] = s1;
    }
}

// ---------------------------------------------------------------------------
// 3b) transpose W once: g_wt[c*128 + k] = W[k*64 + c]
__global__ void wt_kernel(const float* __restrict__ W) {
    int idx = blockIdx.x * blockDim.x + threadIdx.x;
    if (idx < 64 * 128) {
        int c = idx & 63;
        int k = idx >> 6;
        g_wt[c * 128 + k] = W[idx];
    }
}

// ---------------------------------------------------------------------------
// 4) GEMM h = x@W via fma.rn.f32x2, 8 nodes x 8 channels per thread,
//    128 threads/block, 128 nodes/block; + fused a_src/a_dst reduction.
//    h stored fp16 (read by aggregate); logits reduced in fp32.
#define XS_STRIDE 36   // 32 k + pad4 (bank step 4 per node)
#define WS_STRIDE 36   // 32 k + pad4 (bank step 4 per channel)

#define FFMA2(d, a, b) asm("fma.rn.f32x2 %0, %1, %2, %0;" : "+l"(d) : "l"(a), "l"(b))

__global__ __launch_bounds__(128) void gemm_att_kernel(
        const float* __restrict__ x,
        const float* __restrict__ attS,
        const float* __restrict__ attD, int N) {
    __shared__ float ws[64 * WS_STRIDE];    //  9216 B (per-k-chunk W slice)
    __shared__ float xs[128 * XS_STRIDE];   // 18432 B
    int t = threadIdx.x;
    int cg = t & 7;        // channel group: c = cg + 8*i  (i == head!)
    int ng = t >> 3;       // node group:    n = node0 + ng + 16*j
    int node0 = blockIdx.x * 128;

    unsigned long long acc[8][8];
    #pragma unroll
    for (int j = 0; j < 8; j++)
        #pragma unroll
        for (int i = 0; i < 8; i++) acc[j][i] = 0ull;

    for (int kc = 0; kc < 4; kc++) {       // 4 chunks of 32 k
        __syncthreads();
        // stage W chunk: 64c x 32k = 512 float4, 4 per thread (coalesced from g_wt)
        #pragma unroll
        for (int p = 0; p < 4; p++) {
            int idx = t + 128 * p;          // 0..511
            int c  = idx >> 3;
            int k4 = idx & 7;
            float4 v = ((const float4*)g_wt)[c * 32 + kc * 8 + k4];
            *(float4*)&ws[c * WS_STRIDE + k4 * 4] = v;
        }
        // stage x chunk: 128n x 32k = 1024 float4, 8 per thread
        #pragma unroll
        for (int p = 0; p < 8; p++) {
            int idx = t + 128 * p;          // 0..1023
            int nn = idx >> 3;
            int k4 = idx & 7;
            int n = node0 + nn;
            float4 v = make_float4(0.f, 0.f, 0.f, 0.f);
            if (n < N) v = ((const float4*)x)[n * 32 + kc * 8 + k4];
            *(float4*)&xs[nn * XS_STRIDE + k4 * 4] = v;
        }
        __syncthreads();

        #pragma unroll
        for (int k4 = 0; k4 < 8; k4++) {
            ulonglong2 wv[8], xv[8];
            #pragma unroll
            for (int i = 0; i < 8; i++)
                wv[i] = *(const ulonglong2*)&ws[(cg + 8 * i) * WS_STRIDE + k4 * 4];
            #pragma unroll
            for (int j = 0; j < 8; j++)
                xv[j] = *(const ulonglong2*)&xs[(ng + 16 * j) * XS_STRIDE + k4 * 4];
            #pragma unroll
            for (int j = 0; j < 8; j++)
                #pragma unroll
                for (int i = 0; i < 8; i++) {
                    FFMA2(acc[j][i], xv[j].x, wv[i].x);
                    FFMA2(acc[j][i], xv[j].y, wv[i].y);
                }
        }
    }

    // epilogue: unpack, store h (fp16), reduce attention logits per head (fp32)
    float aS[8], aD[8];
    #pragma unroll
    for (int i = 0; i < 8; i++) { aS[i] = attS[cg + 8 * i]; aD[i] = attD[cg + 8 * i]; }

    #pragma unroll
    for (int j = 0; j < 8; j++) {
        int n = node0 + ng + 16 * j;
        bool valid = (n < N);
        #pragma unroll
        for (int i = 0; i < 8; i++) {
            union { unsigned long long u; float2 f; } cv;
            cv.u = acc[j][i];
            float v = cv.f.x + cv.f.y;
            if (valid) g_hh[(long)n * 64 + cg + 8 * i] = __float2half_rn(v);
            float ps = v * aS[i];
            float pd = v * aD[i];
            ps += __shfl_down_sync(0xffffffffu, ps, 4, 8);
            ps += __shfl_down_sync(0xffffffffu, ps, 2, 8);
            ps += __shfl_down_sync(0xffffffffu, ps, 1, 8);
            pd += __shfl_down_sync(0xffffffffu, pd, 4, 8);
            pd += __shfl_down_sync(0xffffffffu, pd, 2, 8);
            pd += __shfl_down_sync(0xffffffffu, pd, 1, 8);
            if (cg == 0 && valid) {
                g_as[n * 8 + i] = ps;
                g_ad[n * 8 + i] = pd;
            }
        }
    }
}

// ---------------------------------------------------------------------------
// 5) warp-per-node softmax + gather, single pass, fp16 h (fp32 accum),
//    edge loop unrolled x2 with independent load chains
__global__ void aggregate_kernel(const float* __restrict__ bias,
                                 float* __restrict__ out, int N) {
    int warp = (blockIdx.x * blockDim.x + threadIdx.x) >> 5;
    int lane = threadIdx.x & 31;
    if (warp >= N) return;
    int n  = warp;
    int c0 = lane * 2;       // 2 channels per lane
    int hl = lane >> 2;      // head for this lane

    float adn = g_ad[n * 8 + hl];
    float asn = g_as[n * 8 + hl];
    int rs = g_row[n];
    int re = rs + g_deg[n];

    // self loop
    float e0 = asn + adn;
    e0 = fmaxf(e0, 0.2f * e0);
    float ex = __expf(e0);
    float ssum = ex;
    float2 hv = __half22float2(*(const __half2*)&g_hh[(long)n * 64 + c0]);
    float a0 = ex * hv.x;
    float a1 = ex * hv.y;

    int i = rs;
    for (; i + 2 <= re; i += 2) {
        int s0 = g_csr[i];
        int s1 = g_csr[i + 1];
        float as0 = g_as[s0 * 8 + hl];
        float as1 = g_as[s1 * 8 + hl];
        __half2 p0 = *(const __half2*)&g_hh[(long)s0 * 64 + c0];
        __half2 p1 = *(const __half2*)&g_hh[(long)s1 * 64 + c0];
        float ea = as0 + adn; ea = fmaxf(ea, 0.2f * ea);
        float eb = as1 + adn; eb = fmaxf(eb, 0.2f * eb);
        float xa = __expf(ea);
        float xb = __expf(eb);
        float2 f0 = __half22float2(p0);
        float2 f1 = __half22float2(p1);
        ssum += xa + xb;
        a0 += xa * f0.x + xb * f1.x;
        a1 += xa * f0.y + xb * f1.y;
    }
    if (i < re) {
        int s = g_csr[i];
        float as = g_as[s * 8 + hl];
        __half2 p = *(const __half2*)&g_hh[(long)s * 64 + c0];
        float e = as + adn; e = fmaxf(e, 0.2f * e);
        float xv = __expf(e);
        float2 f = __half22float2(p);
        ssum += xv;
        a0 += xv * f.x;
        a1 += xv * f.y;
    }
    float inv = 1.0f / ssum;
    out[(long)n * 64 + c0    ] = a0 * inv + bias[c0];
    out[(long)n * 64 + c0 + 1] = a1 * inv + bias[c0 + 1];
}

// ---------------------------------------------------------------------------
extern "C" void kernel_launch(void* const* d_in, const int* in_sizes, int n_in,
                              void* d_out, int out_size) {
    const float* x    = (const float*)d_in[0];
    const int*   ei   = (const int*)d_in[1];
    const float* W    = (const float*)d_in[2];
    const float* attS = (const float*)d_in[3];
    const float* attD = (const float*)d_in[4];
    const float* bias = (const float*)d_in[5];
    float*       out  = (float*)d_out;

    int N = in_sizes[0] / 128;
    int E = in_sizes[1] / 2;
    int Eh = (E + 1) / 2;

    zero_kernel     <<<(N + 255) / 256, 256>>>(N);
    degree_kernel   <<<(Eh + 255) / 256, 256>>>(ei, E, N);
    offsets_kernel  <<<(N + 255) / 256, 256>>>(N);
    scatter_kernel  <<<(Eh + 255) / 256, 256>>>(ei, E, N);
    wt_kernel       <<<(64 * 128 + 255) / 256, 256>>>(W);
    gemm_att_kernel <<<(N + 127) / 128, 128>>>(x, attS, attD, N);
    aggregate_kernel<<<((long)N * 32 + 255) / 256, 256>>>(bias, out, N);
}

// round 8
// speedup vs baseline: 1.7295x; 1.0137x over previous
#include <cuda_runtime.h>
#include <cuda_fp16.h>

#define N_MAX 131072
#define E_MAX 2100000

// scratch (static __device__ arrays; no allocation)
__device__ __half g_hh[N_MAX * 64]; // projected features (fp16 storage, fp32 math)
__device__ float g_as[N_MAX * 8];    // a_src per node/head
__device__ float g_ad[N_MAX * 8];    // a_dst per node/head
__device__ float g_wt[64 * 128];     // W transposed: [c][k]
__device__ int   g_deg[N_MAX];
__device__ int   g_row[N_MAX];       // CSR row start (by dst, unordered bases)
__device__ int   g_cur[N_MAX];
__device__ int   g_csr[E_MAX];       // src node per CSR slot
__device__ int   g_total;

// ---------------------------------------------------------------------------
// 0) zero degree + global counter + transpose W (fused independent prep)
__global__ void prep_kernel(const float* __restrict__ W, int N) {
    int i = blockIdx.x * blockDim.x + threadIdx.x;
    if (i < N) g_deg[i] = 0;
    if (i < 64 * 128) {
        int c = i & 63;
        int k = i >> 6;
        g_wt[c * 128 + k] = W[i];
    }
    if (i == 0) g_total = 0;
}

// 1) in-degree histogram over dst; 4 independent coalesced edges per thread
__global__ void degree_kernel(const int* __restrict__ ei, int E, int N) {
    int q = (E + 3) >> 2;
    int e = blockIdx.x * blockDim.x + threadIdx.x;
    if (e >= q) return;
    int d0 = -1, d1 = -1, d2 = -1, d3 = -1;
    d0 = ei[E + e];
    if (e + q     < E) d1 = ei[E + e + q];
    if (e + 2 * q < E) d2 = ei[E + e + 2 * q];
    if (e + 3 * q < E) d3 = ei[E + e + 3 * q];
    if ((unsigned)d0 < (unsigned)N) atomicAdd(&g_deg[d0], 1);
    if ((unsigned)d1 < (unsigned)N) atomicAdd(&g_deg[d1], 1);
    if ((unsigned)d2 < (unsigned)N) atomicAdd(&g_deg[d2], 1);
    if ((unsigned)d3 < (unsigned)N) atomicAdd(&g_deg[d3], 1);
}

// 2) row-base assignment: warp-aggregated atomic offsets (bases unordered = fine)
__global__ void offsets_kernel(int N) {
    int i = blockIdx.x * blockDim.x + threadIdx.x;
    int lane = threadIdx.x & 31;
    int v = (i < N) ? g_deg[i] : 0;
    int xsum = v;
    #pragma unroll
    for (int o = 1; o < 32; o <<= 1) {
        int y = __shfl_up_sync(0xffffffffu, xsum, o);
        if (lane >= o) xsum += y;
    }
    int tot = __shfl_sync(0xffffffffu, xsum, 31);
    int base = 0;
    if (lane == 31) base = atomicAdd(&g_total, tot);
    base = __shfl_sync(0xffffffffu, base, 31);
    if (i < N) {
        int st = base + xsum - v;
        g_row[i] = st;
        g_cur[i] = st;
    }
}

// 3) scatter edges into CSR slots; 4 independent coalesced edges per thread
__global__ void scatter_kernel(const int* __restrict__ ei, int E, int N) {
    int q = (E + 3) >> 2;
    int e = blockIdx.x * blockDim.x + threadIdx.x;
    if (e >= q) return;
    int s0 = 0, s1 = 0, s2 = 0, s3 = 0;
    int d0 = -1, d1 = -1, d2 = -1, d3 = -1;
    s0 = ei[e];           d0 = ei[E + e];
    if (e + q     < E) { s1 = ei[e + q];     d1 = ei[E + e + q]; }
    if (e + 2 * q < E) { s2 = ei[e + 2 * q]; d2 = ei[E + e + 2 * q]; }
    if (e + 3 * q < E) { s3 = ei[e + 3 * q]; d3 = ei[E + e + 3 * q]; }
    if ((unsigned)d0 < (unsigned)N && (unsigned)s0 < (unsigned)N)
        g_csr[atomicAdd(&g_cur[d0], 1)] = s0;
    if ((unsigned)d1 < (unsigned)N && (unsigned)s1 < (unsigned)N)
        g_csr[atomicAdd(&g_cur[d1], 1)] = s1;
    if ((unsigned)d2 < (unsigned)N && (unsigned)s2 < (unsigned)N)
        g_csr[atomicAdd(&g_cur[d2], 1)] = s2;
    if ((unsigned)d3 < (unsigned)N && (unsigned)s3 < (unsigned)N)
        g_csr[atomicAdd(&g_cur[d3], 1)] = s3;
}

// ---------------------------------------------------------------------------
// 4) GEMM h = x@W via fma.rn.f32x2, 8 nodes x 8 channels per thread,
//    128 threads/block, 128 nodes/block; + fused a_src/a_dst reduction.
//    h stored fp16 (read by aggregate); logits reduced in fp32.
#define XS_STRIDE 36   // 32 k + pad4 (bank step 4 per node)
#define WS_STRIDE 36   // 32 k + pad4 (bank step 4 per channel)

#define FFMA2(d, a, b) asm("fma.rn.f32x2 %0, %1, %2, %0;" : "+l"(d) : "l"(a), "l"(b))

__global__ __launch_bounds__(128) void gemm_att_kernel(
        const float* __restrict__ x,
        const float* __restrict__ attS,
        const float* __restrict__ attD, int N) {
    __shared__ float ws[64 * WS_STRIDE];    //  9216 B (per-k-chunk W slice)
    __shared__ float xs[128 * XS_STRIDE];   // 18432 B
    int t = threadIdx.x;
    int cg = t & 7;        // channel group: c = cg + 8*i  (i == head!)
    int ng = t >> 3;       // node group:    n = node0 + ng + 16*j
    int node0 = blockIdx.x * 128;

    unsigned long long acc[8][8];
    #pragma unroll
    for (int j = 0; j < 8; j++)
        #pragma unroll
        for (int i = 0; i < 8; i++) acc[j][i] = 0ull;

    for (int kc = 0; kc < 4; kc++) {       // 4 chunks of 32 k
        __syncthreads();
        // stage W chunk: 64c x 32k = 512 float4, 4 per thread (coalesced from g_wt)
        #pragma unroll
        for (int p = 0; p < 4; p++) {
            int idx = t + 128 * p;          // 0..511
            int c  = idx >> 3;
            int k4 = idx & 7;
            float4 v = ((const float4*)g_wt)[c * 32 + kc * 8 + k4];
            *(float4*)&ws[c * WS_STRIDE + k4 * 4] = v;
        }
        // stage x chunk: 128n x 32k = 1024 float4, 8 per thread
        #pragma unroll
        for (int p = 0; p < 8; p++) {
            int idx = t + 128 * p;          // 0..1023
            int nn = idx >> 3;
            int k4 = idx & 7;
            int n = node0 + nn;
            float4 v = make_float4(0.f, 0.f, 0.f, 0.f);
            if (n < N) v = ((const float4*)x)[n * 32 + kc * 8 + k4];
            *(float4*)&xs[nn * XS_STRIDE + k4 * 4] = v;
        }
        __syncthreads();

        #pragma unroll
        for (int k4 = 0; k4 < 8; k4++) {
            ulonglong2 wv[8], xv[8];
            #pragma unroll
            for (int i = 0; i < 8; i++)
                wv[i] = *(const ulonglong2*)&ws[(cg + 8 * i) * WS_STRIDE + k4 * 4];
            #pragma unroll
            for (int j = 0; j < 8; j++)
                xv[j] = *(const ulonglong2*)&xs[(ng + 16 * j) * XS_STRIDE + k4 * 4];
            #pragma unroll
            for (int j = 0; j < 8; j++)
                #pragma unroll
                for (int i = 0; i < 8; i++) {
                    FFMA2(acc[j][i], xv[j].x, wv[i].x);
                    FFMA2(acc[j][i], xv[j].y, wv[i].y);
                }
        }
    }

    // epilogue: unpack, store h (fp16), reduce attention logits per head (fp32)
    float aS[8], aD[8];
    #pragma unroll
    for (int i = 0; i < 8; i++) { aS[i] = attS[cg + 8 * i]; aD[i] = attD[cg + 8 * i]; }

    #pragma unroll
    for (int j = 0; j < 8; j++) {
        int n = node0 + ng + 16 * j;
        bool valid = (n < N);
        #pragma unroll
        for (int i = 0; i < 8; i++) {
            union { unsigned long long u; float2 f; } cv;
            cv.u = acc[j][i];
            float v = cv.f.x + cv.f.y;
            if (valid) g_hh[(long)n * 64 + cg + 8 * i] = __float2half_rn(v);
            float ps = v * aS[i];
            float pd = v * aD[i];
            ps += __shfl_down_sync(0xffffffffu, ps, 4, 8);
            ps += __shfl_down_sync(0xffffffffu, ps, 2, 8);
            ps += __shfl_down_sync(0xffffffffu, ps, 1, 8);
            pd += __shfl_down_sync(0xffffffffu, pd, 4, 8);
            pd += __shfl_down_sync(0xffffffffu, pd, 2, 8);
            pd += __shfl_down_sync(0xffffffffu, pd, 1, 8);
            if (cg == 0 && valid) {
                g_as[n * 8 + i] = ps;
                g_ad[n * 8 + i] = pd;
            }
        }
    }
}

// ---------------------------------------------------------------------------
// 5) warp-per-node softmax + gather; HALF-WARP per edge (2 edges/iteration):
//    lanes 0-15 process edge i, lanes 16-31 edge i+1; each lane holds 4 channels.
//    srcs come from a 32-edge register batch (1 coalesced load / 32 edges + 1
//    shfl per 2 edges). Per 2 edges: 1 'as' warp-load + 1 'h' warp-load.
__global__ void aggregate_kernel(const float* __restrict__ bias,
                                 float* __restrict__ out, int N) {
    int warp = (blockIdx.x * blockDim.x + threadIdx.x) >> 5;
    int lane = threadIdx.x & 31;
    if (warp >= N) return;
    int n    = warp;
    int l16  = lane & 15;
    int half = lane >> 4;
    int c0   = l16 * 4;        // 4 channels per lane
    int hl   = l16 >> 1;       // head for this lane (4 ch within one head)

    float adn = g_ad[n * 8 + hl];
    float asn = g_as[n * 8 + hl];
    int rs = g_row[n];
    int re = rs + g_deg[n];

    float a0 = 0.f, a1 = 0.f, a2 = 0.f, a3 = 0.f, ssum = 0.f;
    if (half == 0) {   // self loop on first half-warp
        float e0 = asn + adn;
        e0 = fmaxf(e0, 0.2f * e0);
        float ex = __expf(e0);
        uint2 u = *(const uint2*)&g_hh[(long)n * 64 + c0];
        float2 f01 = __half22float2(*(__half2*)&u.x);
        float2 f23 = __half22float2(*(__half2*)&u.y);
        ssum = ex;
        a0 = ex * f01.x; a1 = ex * f01.y;
        a2 = ex * f23.x; a3 = ex * f23.y;
    }

    for (int base = rs; base < re; base += 32) {
        int cnt = re - base; if (cnt > 32) cnt = 32;
        int sv = 0;
        if (lane < cnt) sv = g_csr[base + lane];
        for (int it = 0; it < cnt; it += 2) {
            int idx = it + half;
            int s = __shfl_sync(0xffffffffu, sv, idx);  // 0 if idx>=cnt (sv=0 there)
            float as = g_as[s * 8 + hl];
            uint2 u = *(const uint2*)&g_hh[(long)s * 64 + c0];
            float e = as + adn;
            e = fmaxf(e, 0.2f * e);
            float xv = __expf(e);
            if (idx >= cnt) xv = 0.f;     // mask tail lane-group
            float2 f01 = __half22float2(*(__half2*)&u.x);
            float2 f23 = __half22float2(*(__half2*)&u.y);
            ssum += xv;
            a0 += xv * f01.x; a1 += xv * f01.y;
            a2 += xv * f23.x; a3 += xv * f23.y;
        }
    }

    // combine halves
    a0   += __shfl_down_sync(0xffffffffu, a0,   16);
    a1   += __shfl_down_sync(0xffffffffu, a1,   16);
    a2   += __shfl_down_sync(0xffffffffu, a2,   16);
    a3   += __shfl_down_sync(0xffffffffu, a3,   16);
    ssum += __shfl_down_sync(0xffffffffu, ssum, 16);

    if (half == 0) {
        float inv = 1.0f / ssum;
        float4 bv = ((const float4*)bias)[l16];
        float4 o;
        o.x = a0 * inv + bv.x;
        o.y = a1 * inv + bv.y;
        o.z = a2 * inv + bv.z;
        o.w = a3 * inv + bv.w;
        ((float4*)out)[(long)n * 16 + l16] = o;
    }
}

// ---------------------------------------------------------------------------
extern "C" void kernel_launch(void* const* d_in, const int* in_sizes, int n_in,
                              void* d_out, int out_size) {
    const float* x    = (const float*)d_in[0];
    const int*   ei   = (const int*)d_in[1];
    const float* W    = (const float*)d_in[2];
    const float* attS = (const float*)d_in[3];
    const float* attD = (const float*)d_in[4];
    const float* bias = (const float*)d_in[5];
    float*       out  = (float*)d_out;

    int N = in_sizes[0] / 128;
    int E = in_sizes[1] / 2;
    int Eq = (E + 3) / 4;
    int P  = (N > 64 * 128) ? N : 64 * 128;

    prep_kernel     <<<(P + 255) / 256, 256>>>(W, N);
    degree_kernel   <<<(Eq + 255) / 256, 256>>>(ei, E, N);
    offsets_kernel  <<<(N + 255) / 256, 256>>>(N);
    scatter_kernel  <<<(Eq + 255) / 256, 256>>>(ei, E, N);
    gemm_att_kernel <<<(N + 127) / 128, 128>>>(x, attS, attD, N);
    aggregate_kernel<<<((long)N * 32 + 255) / 256, 256>>>(bias, out, N);
}